// round 16
// baseline (speedup 1.0000x reference)
#include <cuda_runtime.h>
#include <cuda_fp16.h>
#include <stdint.h>

#define MAXN 100000
#define MAXE 3200000
#define FDIM 128
#define SCAN_CHUNK 1024
#define MAX_SCAN_BLOCKS 128  // ceil(100000/1024)=98
#define FIX_SCALE 1048576.0f          // 2^20 fixed-point for weighted degree
#define MASK52 ((1ULL << 52) - 1)

// ------------------- device scratch -------------------
// NOTE: these symbols must ONLY be referenced from device code. Passing them
// as kernel args from host yields the host shadow symbol, which GB300's ATS
// serves from Grace DRAM at ~200 GB/s (the R2-R5 17.9ms bug).
__device__ unsigned long long g_dc[MAXN];     // [count:52..63][deg*2^20:0..51]
__device__ int   g_rowptr[MAXN + 1];          // scan: row start; after scatter: row END
__device__ int   g_partial[MAX_SCAN_BLOCKS];
__device__ int   g_blockoff[MAX_SCAN_BLOCKS];
__device__ __align__(16) int2 g_edge[MAXE];   // {src, __float_as_int(edge weight)}
__device__ __align__(16) __half g_hf[(size_t)MAXN * FDIM];  // dinv-scaled gemm out (fp16)
__device__ __align__(16) float  g_h2[(size_t)MAXN * FDIM];  // spmm1 out (fp32)

// ------------------- dtype sniff helper (int64 vs int32 edge_index) -------------------
__device__ __forceinline__ int sniff_is64(const void* ei_raw, int N) {
    const long long* p64 = (const long long*)ei_raw;
    int ok = 1;
#pragma unroll
    for (int i = 0; i < 4; i++) {
        long long v = p64[i];
        if (v < 0 || v >= (long long)N) ok = 0;
    }
    return ok;
}

__device__ __forceinline__ float unpack_dinv(unsigned long long pk) {
    return rsqrtf((float)(pk & MASK52) * (1.0f / FIX_SCALE));
}

// ------------------- init: deg starts at self-loop weight 1.0; count at 0 ----------
__global__ void k_init(int N) {
    int i = blockIdx.x * blockDim.x + threadIdx.x;
    if (i < N) g_dc[i] = (unsigned long long)(1u << 20);
}

// ------------------- degree+count: ONE packed 64-bit atomic; 2 edges/thread ---------
__global__ void k_degcount(const void* __restrict__ ei_raw,
                           const float* __restrict__ ew, int E, int N) {
    __shared__ int is64;
    if (threadIdx.x == 0) is64 = sniff_is64(ei_raw, N);
    __syncthreads();
    int t = blockIdx.x * blockDim.x + threadIdx.x;
    int e = t * 2;
    if (e >= E) return;
    int c0, c1 = -1;
    if (is64) {
        const long long* p64 = (const long long*)ei_raw;
        c0 = (int)p64[(size_t)E + e];
        if (e + 1 < E) c1 = (int)p64[(size_t)E + e + 1];
    } else {
        const int* p32 = (const int*)ei_raw;
        int2 cc = *(const int2*)(p32 + (size_t)E + e);   // E even -> aligned
        c0 = cc.x;
        if (e + 1 < E) c1 = cc.y;
    }
    float2 wv = *(const float2*)(ew + e);
    unsigned long long pk0 =
        (1ULL << 52) | (unsigned long long)__float2uint_rn(wv.x * FIX_SCALE);
    atomicAdd(&g_dc[c0], pk0);
    if (c1 >= 0) {
        unsigned long long pk1 =
            (1ULL << 52) | (unsigned long long)__float2uint_rn(wv.y * FIX_SCALE);
        atomicAdd(&g_dc[c1], pk1);
    }
}

// ------------------- scan pass 1: per-block exclusive scan of counts -------------------
__global__ void k_scan1(int N) {
    __shared__ int sm[256];
    int t = threadIdx.x;               // 256 threads, 4 elems each -> 1024 per block
    int base = blockIdx.x * SCAN_CHUNK + t * 4;
    int c0 = (base + 0 < N) ? (int)(g_dc[base + 0] >> 52) : 0;
    int c1 = (base + 1 < N) ? (int)(g_dc[base + 1] >> 52) : 0;
    int c2 = (base + 2 < N) ? (int)(g_dc[base + 2] >> 52) : 0;
    int c3 = (base + 3 < N) ? (int)(g_dc[base + 3] >> 52) : 0;
    int tsum = c0 + c1 + c2 + c3;
    sm[t] = tsum;
    __syncthreads();
    for (int off = 1; off < 256; off <<= 1) {
        int v = (t >= off) ? sm[t - off] : 0;
        __syncthreads();
        sm[t] += v;
        __syncthreads();
    }
    int pre = sm[t] - tsum;
    if (base + 0 < N) g_rowptr[base + 0] = pre;
    if (base + 1 < N) g_rowptr[base + 1] = pre + c0;
    if (base + 2 < N) g_rowptr[base + 2] = pre + c0 + c1;
    if (base + 3 < N) g_rowptr[base + 3] = pre + c0 + c1 + c2;
    if (t == 255) g_partial[blockIdx.x] = sm[255];
}

// ------------------- scan pass 2: scan block partials (single block) -------------------
__global__ void k_scan2(int nb) {
    __shared__ int sm[MAX_SCAN_BLOCKS];
    int t = threadIdx.x;               // blockDim = MAX_SCAN_BLOCKS
    int v = (t < nb) ? g_partial[t] : 0;
    sm[t] = v;
    __syncthreads();
    for (int off = 1; off < MAX_SCAN_BLOCKS; off <<= 1) {
        int u = (t >= off) ? sm[t - off] : 0;
        __syncthreads();
        sm[t] += u;
        __syncthreads();
    }
    if (t < nb) g_blockoff[t] = sm[t] - v;
}

// ------------------- scan pass 3: add block offsets -------------------
__global__ void k_scan3(int N) {
    int i = blockIdx.x * blockDim.x + threadIdx.x;
    if (i < N) g_rowptr[i] += g_blockoff[i >> 10];
}

// ------------------- scatter (destructive cursor): rowptr[c] -> row END -------------
__global__ void k_scatter(const void* __restrict__ ei_raw,
                          const float* __restrict__ ew, int E, int N) {
    __shared__ int is64;
    if (threadIdx.x == 0) is64 = sniff_is64(ei_raw, N);
    __syncthreads();
    int t = blockIdx.x * blockDim.x + threadIdx.x;
    int e = t * 2;
    if (e >= E) return;
    int r0, c0, r1 = -1, c1 = -1;
    if (is64) {
        const long long* p64 = (const long long*)ei_raw;
        r0 = (int)p64[e];
        c0 = (int)p64[(size_t)E + e];
        if (e + 1 < E) {
            r1 = (int)p64[e + 1];
            c1 = (int)p64[(size_t)E + e + 1];
        }
    } else {
        const int* p32 = (const int*)ei_raw;
        int2 rr = *(const int2*)(p32 + e);
        int2 cc = *(const int2*)(p32 + (size_t)E + e);
        r0 = rr.x; c0 = cc.x;
        if (e + 1 < E) { r1 = rr.y; c1 = cc.y; }
    }
    float2 wv = *(const float2*)(ew + e);
    int pos0 = atomicAdd(&g_rowptr[c0], 1);
    g_edge[pos0] = make_int2(r0, __float_as_int(wv.x));
    if (r1 >= 0) {
        int pos1 = atomicAdd(&g_rowptr[c1], 1);
        g_edge[pos1] = make_int2(r1, __float_as_int(wv.y));
    }
}

// ------------------- TF32 helpers -------------------
// RNA-round fp32 bits to tf32: +half-ulp of the 13 dropped bits. (Truncation
// would give a systematic -2^-10 bias that accumulates over K=128 -> ~1e-3.)
__device__ __forceinline__ uint32_t rna_tf32(float x) {
    return __float_as_uint(x) + 0x1000u;
}

__device__ __forceinline__ void mma_tf32(float& c0, float& c1, float& c2, float& c3,
                                         uint32_t a0, uint32_t a1, uint32_t a2, uint32_t a3,
                                         uint32_t b0, uint32_t b1) {
    asm volatile(
        "mma.sync.aligned.m16n8k8.row.col.f32.tf32.tf32.f32 "
        "{%0,%1,%2,%3}, {%4,%5,%6,%7}, {%8,%9}, {%0,%1,%2,%3};"
        : "+f"(c0), "+f"(c1), "+f"(c2), "+f"(c3)
        : "r"(a0), "r"(a1), "r"(a2), "r"(a3), "r"(b0), "r"(b1));
}

__device__ __forceinline__ void cp_async16(void* smem_dst, const void* gsrc, int bytes) {
    uint32_t d = (uint32_t)__cvta_generic_to_shared(smem_dst);
    asm volatile("cp.async.cg.shared.global [%0], [%1], 16, %2;"
                 :: "r"(d), "l"(gsrc), "r"(bytes));
}

// ------------------- TF32 tensor GEMM: g_hf[M,128] = dinv ⊙ (A[M,128] @ W[128,128]) --
// 64x128 block tile, 8 warps in 2x4; warp tile 32x32. 3-stage cp.async pipeline,
// k-chunks of 16, ONE __syncthreads per chunk. Epilogue folds dinv[row] into fp16 out.
#define AS 20    // A tile row stride (16 k + 4 pad)
#define WS 136   // W tile row stride
__global__ void __launch_bounds__(256) k_gemm(const float* __restrict__ Aopt,
                                              const float* __restrict__ W, int M) {
    const float* A = Aopt ? Aopt : g_h2;
    __half* C = g_hf;
    __shared__ float xs[3][64 * AS];    // 3*64*20*4  = 15360 B
    __shared__ float ws[3][16 * WS];    // 3*16*136*4 = 26112 B

    int tid = threadIdx.x;
    int wid = tid >> 5;
    int lane = tid & 31;
    int grp = lane >> 2;               // 0..7
    int sub = lane & 3;                // 0..3
    int m0 = blockIdx.x * 64;
    int wr = (wid >> 2) * 32;          // warp row base (0,32)
    int wc = (wid & 3) * 32;           // warp col base (0,32,64,96)

    float c[2][4][4];
#pragma unroll
    for (int f = 0; f < 2; f++)
#pragma unroll
        for (int nt = 0; nt < 4; nt++)
#pragma unroll
            for (int j = 0; j < 4; j++) c[f][nt][j] = 0.0f;

    auto loadA = [&](int k0, int buf) {
        int r = tid >> 2;
        int q = tid & 3;
        int bytes = (m0 + r < M) ? 16 : 0;
        cp_async16(&xs[buf][r * AS + q * 4],
                   A + (size_t)(m0 + r) * 128 + k0 + q * 4, bytes);
    };
    auto loadW = [&](int k0, int buf) {
#pragma unroll
        for (int i = 0; i < 2; i++) {
            int idx = tid + i * 256;
            int r = idx >> 5;
            int q = idx & 31;
            cp_async16(&ws[buf][r * WS + q * 4],
                       W + (size_t)(k0 + r) * 128 + q * 4, 16);
        }
    };

    loadA(0, 0);  loadW(0, 0);  asm volatile("cp.async.commit_group;");
    loadA(16, 1); loadW(16, 1); asm volatile("cp.async.commit_group;");

#pragma unroll
    for (int ch = 0; ch < 8; ch++) {
        int buf = ch % 3;
        if (ch < 7) asm volatile("cp.async.wait_group 1;");
        else        asm volatile("cp.async.wait_group 0;");
        __syncthreads();
        if (ch + 2 < 8) {
            int nb = (ch + 2) % 3;
            loadA((ch + 2) * 16, nb);
            loadW((ch + 2) * 16, nb);
            asm volatile("cp.async.commit_group;");
        }

#pragma unroll
        for (int kk = 0; kk < 2; kk++) {
            int kb = kk * 8;
            uint32_t a[2][4];
#pragma unroll
            for (int f = 0; f < 2; f++) {
                int rb = wr + f * 16;
                a[f][0] = rna_tf32(xs[buf][(rb + grp) * AS + kb + sub]);
                a[f][1] = rna_tf32(xs[buf][(rb + grp + 8) * AS + kb + sub]);
                a[f][2] = rna_tf32(xs[buf][(rb + grp) * AS + kb + sub + 4]);
                a[f][3] = rna_tf32(xs[buf][(rb + grp + 8) * AS + kb + sub + 4]);
            }
#pragma unroll
            for (int nt = 0; nt < 4; nt++) {
                uint32_t b0 = rna_tf32(ws[buf][(kb + sub) * WS + wc + nt * 8 + grp]);
                uint32_t b1 = rna_tf32(ws[buf][(kb + sub + 4) * WS + wc + nt * 8 + grp]);
                mma_tf32(c[0][nt][0], c[0][nt][1], c[0][nt][2], c[0][nt][3],
                         a[0][0], a[0][1], a[0][2], a[0][3], b0, b1);
                mma_tf32(c[1][nt][0], c[1][nt][1], c[1][nt][2], c[1][nt][3],
                         a[1][0], a[1][1], a[1][2], a[1][3], b0, b1);
            }
        }
    }

    // epilogue: scale row by dinv[row], emit fp16
#pragma unroll
    for (int f = 0; f < 2; f++) {
        int r0 = m0 + wr + f * 16 + grp;
        int r1 = r0 + 8;
        float d0 = (r0 < M) ? unpack_dinv(g_dc[r0]) : 0.0f;
        float d1 = (r1 < M) ? unpack_dinv(g_dc[r1]) : 0.0f;
#pragma unroll
        for (int nt = 0; nt < 4; nt++) {
            int cb = wc + nt * 8 + 2 * sub;
            if (r0 < M)
                *(half2*)(C + (size_t)r0 * 128 + cb) =
                    __floats2half2_rn(d0 * c[f][nt][0], d0 * c[f][nt][1]);
            if (r1 < M)
                *(half2*)(C + (size_t)r1 * 128 + cb) =
                    __floats2half2_rn(d1 * c[f][nt][2], d1 * c[f][nt][3]);
        }
    }
}

// ------------------- SpMM: out[c,:] = dinv[c]*(sum w*hf[src,:] + hf[c,:]) + b -------
// After destructive scatter: rowptr[c] = END of row c; beg = rowptr[c-1] (0 for c=0).
__global__ void __launch_bounds__(256) k_spmm(const float* __restrict__ bias,
                                              float* outOpt, int N, int doRelu) {
    const uint2* h = (const uint2*)g_hf;
    float* out = outOpt ? outOpt : g_h2;
    int warp = (blockIdx.x * blockDim.x + threadIdx.x) >> 5;
    int lane = threadIdx.x & 31;
    if (warp >= N) return;
    int beg = (warp == 0) ? 0 : g_rowptr[warp - 1];
    int end = g_rowptr[warp];

    float4 acc = make_float4(0.f, 0.f, 0.f, 0.f);
    int e = beg;

#define GATHER_FMA(P, V)                                            \
    do {                                                            \
        float2 f0 = __half22float2(*(const half2*)&(P).x);          \
        float2 f1 = __half22float2(*(const half2*)&(P).y);          \
        acc.x += (V) * f0.x; acc.y += (V) * f0.y;                   \
        acc.z += (V) * f1.x; acc.w += (V) * f1.y;                   \
    } while (0)

    if ((e & 1) && e < end) {
        int2 p = g_edge[e];
        uint2 hv = h[(size_t)p.x * 32 + lane];
        GATHER_FMA(hv, __int_as_float(p.y));
        e++;
    }

    for (; e + 8 <= end; e += 8) {
        int4 q0 = *(const int4*)&g_edge[e + 0];
        int4 q1 = *(const int4*)&g_edge[e + 2];
        int4 q2 = *(const int4*)&g_edge[e + 4];
        int4 q3 = *(const int4*)&g_edge[e + 6];
        uint2 h0 = h[(size_t)q0.x * 32 + lane];
        uint2 h1 = h[(size_t)q0.z * 32 + lane];
        uint2 h2 = h[(size_t)q1.x * 32 + lane];
        uint2 h3 = h[(size_t)q1.z * 32 + lane];
        uint2 h4 = h[(size_t)q2.x * 32 + lane];
        uint2 h5 = h[(size_t)q2.z * 32 + lane];
        uint2 h6 = h[(size_t)q3.x * 32 + lane];
        uint2 h7 = h[(size_t)q3.z * 32 + lane];
        GATHER_FMA(h0, __int_as_float(q0.y));
        GATHER_FMA(h1, __int_as_float(q0.w));
        GATHER_FMA(h2, __int_as_float(q1.y));
        GATHER_FMA(h3, __int_as_float(q1.w));
        GATHER_FMA(h4, __int_as_float(q2.y));
        GATHER_FMA(h5, __int_as_float(q2.w));
        GATHER_FMA(h6, __int_as_float(q3.y));
        GATHER_FMA(h7, __int_as_float(q3.w));
    }

    for (; e + 2 <= end; e += 2) {
        int4 q0 = *(const int4*)&g_edge[e];
        uint2 h0 = h[(size_t)q0.x * 32 + lane];
        uint2 h1 = h[(size_t)q0.z * 32 + lane];
        GATHER_FMA(h0, __int_as_float(q0.y));
        GATHER_FMA(h1, __int_as_float(q0.w));
    }
    if (e < end) {
        int2 p = g_edge[e];
        uint2 hv = h[(size_t)p.x * 32 + lane];
        GATHER_FMA(hv, __int_as_float(p.y));
    }

    // self-loop: own row, weight 1.0 (coalesced read)
    {
        uint2 hv = h[(size_t)warp * 32 + lane];
        GATHER_FMA(hv, 1.0f);
    }
#undef GATHER_FMA

    float dinv_c = unpack_dinv(g_dc[warp]);
    float4 b = ((const float4*)bias)[lane];
    float4 r;
    r.x = dinv_c * acc.x + b.x;
    r.y = dinv_c * acc.y + b.y;
    r.z = dinv_c * acc.z + b.z;
    r.w = dinv_c * acc.w + b.w;
    if (doRelu) {
        r.x = fmaxf(r.x, 0.f);
        r.y = fmaxf(r.y, 0.f);
        r.z = fmaxf(r.z, 0.f);
        r.w = fmaxf(r.w, 0.f);
    }
    *(float4*)(out + (size_t)warp * 128 + lane * 4) = r;
}

// ------------------- launch -------------------
// Fork-join DAG:
//   main: init -> degcount -> [fork] scan1 -> scan2 -> scan3 -> scatter -> [join] spmm1 -> gemm2 -> spmm2
//   side:                       gemm1 (needs only g_dc)
extern "C" void kernel_launch(void* const* d_in, const int* in_sizes, int n_in,
                              void* d_out, int out_size) {
    const float* x  = (const float*)d_in[0];
    const void*  ei = (const void*)d_in[1];
    const float* ew = (const float*)d_in[2];
    const float* W1 = (const float*)d_in[3];
    const float* b1 = (const float*)d_in[4];
    const float* W2 = (const float*)d_in[5];
    const float* b2 = (const float*)d_in[6];
    float* out = (float*)d_out;

    const int E = in_sizes[2];          // 3200000
    const int N = in_sizes[0] / FDIM;   // 100000

    // Created once on the first (uncaptured correctness) call; reused under capture.
    static cudaStream_t s1 = nullptr;
    static cudaEvent_t evFork = nullptr, evJoin = nullptr;
    if (s1 == nullptr) {
        cudaStreamCreateWithFlags(&s1, cudaStreamNonBlocking);
        cudaEventCreateWithFlags(&evFork, cudaEventDisableTiming);
        cudaEventCreateWithFlags(&evJoin, cudaEventDisableTiming);
    }

    int gemmGrid = (N + 63) / 64;
    int spmmGrid = (N * 32 + 255) / 256;
    int nb = (N + SCAN_CHUNK - 1) / SCAN_CHUNK;
    int edgeGrid = ((E + 1) / 2 + 255) / 256;

    k_init<<<(N + 255) / 256, 256>>>(N);
    k_degcount<<<edgeGrid, 256>>>(ei, ew, E, N);

    // fork: gemm1 only needs g_dc (degcount) — overlap with CSR build
    cudaEventRecord(evFork, 0);
    cudaStreamWaitEvent(s1, evFork, 0);
    k_gemm<<<gemmGrid, 256, 0, s1>>>(x, W1, N);
    cudaEventRecord(evJoin, s1);

    k_scan1<<<nb, 256>>>(N);
    k_scan2<<<1, MAX_SCAN_BLOCKS>>>(nb);
    k_scan3<<<(N + 255) / 256, 256>>>(N);
    k_scatter<<<edgeGrid, 256>>>(ei, ew, E, N);

    // join: spmm1 needs both scatter (CSR) and gemm1 (g_hf)
    cudaStreamWaitEvent(0, evJoin, 0);
    k_spmm<<<spmmGrid, 256>>>(b1, nullptr, N, 1);   // g_hf -> g_h2
    k_gemm<<<gemmGrid, 256>>>(nullptr, W2, N);      // g_h2 -> g_hf
    k_spmm<<<spmmGrid, 256>>>(b2, out, N, 0);       // g_hf -> out
}

// round 17
// speedup vs baseline: 1.0071x; 1.0071x over previous
#include <cuda_runtime.h>
#include <cuda_fp16.h>
#include <stdint.h>

#define MAXN 100000
#define MAXE 3200000
#define FDIM 128
#define SCAN_CHUNK 1024
#define MAX_SCAN_BLOCKS 128  // ceil(100000/1024)=98
#define FIX_SCALE 1048576.0f          // 2^20 fixed-point for weighted degree
#define MASK52 ((1ULL << 52) - 1)

// ------------------- device scratch -------------------
// NOTE: these symbols must ONLY be referenced from device code. Passing them
// as kernel args from host yields the host shadow symbol, which GB300's ATS
// serves from Grace DRAM at ~200 GB/s (the R2-R5 17.9ms bug).
__device__ unsigned long long g_dc[MAXN];     // [count:52..63][deg*2^20:0..51]
__device__ int   g_rowptr[MAXN + 1];          // scan: row start; after scatter: row END
__device__ int   g_partial[MAX_SCAN_BLOCKS];
__device__ int   g_blockoff[MAX_SCAN_BLOCKS];
__device__ __align__(16) int2 g_edge[MAXE];   // {src, __float_as_int(edge weight)}
__device__ __align__(16) __half g_hf[(size_t)MAXN * FDIM];  // dinv-scaled gemm out (fp16)
__device__ __align__(16) float  g_h2[(size_t)MAXN * FDIM];  // spmm1 out (fp32)

// ------------------- dtype sniff helper (int64 vs int32 edge_index) -------------------
__device__ __forceinline__ int sniff_is64(const void* ei_raw, int N) {
    const long long* p64 = (const long long*)ei_raw;
    int ok = 1;
#pragma unroll
    for (int i = 0; i < 4; i++) {
        long long v = p64[i];
        if (v < 0 || v >= (long long)N) ok = 0;
    }
    return ok;
}

__device__ __forceinline__ float unpack_dinv(unsigned long long pk) {
    return rsqrtf((float)(pk & MASK52) * (1.0f / FIX_SCALE));
}

// ------------------- init: deg starts at self-loop weight 1.0; count at 0 ----------
__global__ void k_init(int N) {
    int i = blockIdx.x * blockDim.x + threadIdx.x;
    if (i < N) g_dc[i] = (unsigned long long)(1u << 20);
}

// ------------------- degree+count: ONE packed 64-bit atomic; 2 edges/thread ---------
__global__ void k_degcount(const void* __restrict__ ei_raw,
                           const float* __restrict__ ew, int E, int N) {
    __shared__ int is64;
    if (threadIdx.x == 0) is64 = sniff_is64(ei_raw, N);
    __syncthreads();
    int t = blockIdx.x * blockDim.x + threadIdx.x;
    int e = t * 2;
    if (e >= E) return;
    int c0, c1 = -1;
    if (is64) {
        const long long* p64 = (const long long*)ei_raw;
        c0 = (int)p64[(size_t)E + e];
        if (e + 1 < E) c1 = (int)p64[(size_t)E + e + 1];
    } else {
        const int* p32 = (const int*)ei_raw;
        int2 cc = *(const int2*)(p32 + (size_t)E + e);   // E even -> aligned
        c0 = cc.x;
        if (e + 1 < E) c1 = cc.y;
    }
    float2 wv = *(const float2*)(ew + e);
    unsigned long long pk0 =
        (1ULL << 52) | (unsigned long long)__float2uint_rn(wv.x * FIX_SCALE);
    atomicAdd(&g_dc[c0], pk0);
    if (c1 >= 0) {
        unsigned long long pk1 =
            (1ULL << 52) | (unsigned long long)__float2uint_rn(wv.y * FIX_SCALE);
        atomicAdd(&g_dc[c1], pk1);
    }
}

// ------------------- scan pass 1: per-block exclusive scan of counts -------------------
__global__ void k_scan1(int N) {
    __shared__ int sm[256];
    int t = threadIdx.x;               // 256 threads, 4 elems each -> 1024 per block
    int base = blockIdx.x * SCAN_CHUNK + t * 4;
    int c0 = (base + 0 < N) ? (int)(g_dc[base + 0] >> 52) : 0;
    int c1 = (base + 1 < N) ? (int)(g_dc[base + 1] >> 52) : 0;
    int c2 = (base + 2 < N) ? (int)(g_dc[base + 2] >> 52) : 0;
    int c3 = (base + 3 < N) ? (int)(g_dc[base + 3] >> 52) : 0;
    int tsum = c0 + c1 + c2 + c3;
    sm[t] = tsum;
    __syncthreads();
    for (int off = 1; off < 256; off <<= 1) {
        int v = (t >= off) ? sm[t - off] : 0;
        __syncthreads();
        sm[t] += v;
        __syncthreads();
    }
    int pre = sm[t] - tsum;
    if (base + 0 < N) g_rowptr[base + 0] = pre;
    if (base + 1 < N) g_rowptr[base + 1] = pre + c0;
    if (base + 2 < N) g_rowptr[base + 2] = pre + c0 + c1;
    if (base + 3 < N) g_rowptr[base + 3] = pre + c0 + c1 + c2;
    if (t == 255) g_partial[blockIdx.x] = sm[255];
}

// ------------------- scan pass 2: scan block partials (single block) -------------------
__global__ void k_scan2(int nb) {
    __shared__ int sm[MAX_SCAN_BLOCKS];
    int t = threadIdx.x;               // blockDim = MAX_SCAN_BLOCKS
    int v = (t < nb) ? g_partial[t] : 0;
    sm[t] = v;
    __syncthreads();
    for (int off = 1; off < MAX_SCAN_BLOCKS; off <<= 1) {
        int u = (t >= off) ? sm[t - off] : 0;
        __syncthreads();
        sm[t] += u;
        __syncthreads();
    }
    if (t < nb) g_blockoff[t] = sm[t] - v;
}

// ------------------- scan pass 3: add block offsets -------------------
__global__ void k_scan3(int N) {
    int i = blockIdx.x * blockDim.x + threadIdx.x;
    if (i < N) g_rowptr[i] += g_blockoff[i >> 10];
}

// ------------------- scatter (destructive cursor): rowptr[c] -> row END -------------
__global__ void k_scatter(const void* __restrict__ ei_raw,
                          const float* __restrict__ ew, int E, int N) {
    __shared__ int is64;
    if (threadIdx.x == 0) is64 = sniff_is64(ei_raw, N);
    __syncthreads();
    int t = blockIdx.x * blockDim.x + threadIdx.x;
    int e = t * 2;
    if (e >= E) return;
    int r0, c0, r1 = -1, c1 = -1;
    if (is64) {
        const long long* p64 = (const long long*)ei_raw;
        r0 = (int)p64[e];
        c0 = (int)p64[(size_t)E + e];
        if (e + 1 < E) {
            r1 = (int)p64[e + 1];
            c1 = (int)p64[(size_t)E + e + 1];
        }
    } else {
        const int* p32 = (const int*)ei_raw;
        int2 rr = *(const int2*)(p32 + e);
        int2 cc = *(const int2*)(p32 + (size_t)E + e);
        r0 = rr.x; c0 = cc.x;
        if (e + 1 < E) { r1 = rr.y; c1 = cc.y; }
    }
    float2 wv = *(const float2*)(ew + e);
    int pos0 = atomicAdd(&g_rowptr[c0], 1);
    g_edge[pos0] = make_int2(r0, __float_as_int(wv.x));
    if (r1 >= 0) {
        int pos1 = atomicAdd(&g_rowptr[c1], 1);
        g_edge[pos1] = make_int2(r1, __float_as_int(wv.y));
    }
}

// ------------------- TF32 helpers -------------------
// RNA-round fp32 bits to tf32: +half-ulp of the 13 dropped bits. (Truncation
// would give a systematic -2^-10 bias that accumulates over K=128 -> ~1e-3.)
__device__ __forceinline__ uint32_t rna_tf32(float x) {
    return __float_as_uint(x) + 0x1000u;
}

__device__ __forceinline__ void mma_tf32(float& c0, float& c1, float& c2, float& c3,
                                         uint32_t a0, uint32_t a1, uint32_t a2, uint32_t a3,
                                         uint32_t b0, uint32_t b1) {
    asm volatile(
        "mma.sync.aligned.m16n8k8.row.col.f32.tf32.tf32.f32 "
        "{%0,%1,%2,%3}, {%4,%5,%6,%7}, {%8,%9}, {%0,%1,%2,%3};"
        : "+f"(c0), "+f"(c1), "+f"(c2), "+f"(c3)
        : "r"(a0), "r"(a1), "r"(a2), "r"(a3), "r"(b0), "r"(b1));
}

__device__ __forceinline__ void cp_async16(void* smem_dst, const void* gsrc, int bytes) {
    uint32_t d = (uint32_t)__cvta_generic_to_shared(smem_dst);
    asm volatile("cp.async.cg.shared.global [%0], [%1], 16, %2;"
                 :: "r"(d), "l"(gsrc), "r"(bytes));
}

// ------------------- TF32 tensor GEMM: g_hf[M,128] = dinv ⊙ (A[M,128] @ W[128,128]) --
// 64x128 block tile, 8 warps in 2x4; warp tile 32x32. 3-stage cp.async pipeline,
// k-chunks of 16, ONE __syncthreads per chunk. Epilogue folds dinv[row] into fp16 out.
#define AS 20    // A tile row stride (16 k + 4 pad)
#define WS 136   // W tile row stride
__global__ void __launch_bounds__(256) k_gemm(const float* __restrict__ Aopt,
                                              const float* __restrict__ W, int M) {
    const float* A = Aopt ? Aopt : g_h2;
    __half* C = g_hf;
    __shared__ float xs[3][64 * AS];    // 3*64*20*4  = 15360 B
    __shared__ float ws[3][16 * WS];    // 3*16*136*4 = 26112 B

    int tid = threadIdx.x;
    int wid = tid >> 5;
    int lane = tid & 31;
    int grp = lane >> 2;               // 0..7
    int sub = lane & 3;                // 0..3
    int m0 = blockIdx.x * 64;
    int wr = (wid >> 2) * 32;          // warp row base (0,32)
    int wc = (wid & 3) * 32;           // warp col base (0,32,64,96)

    float c[2][4][4];
#pragma unroll
    for (int f = 0; f < 2; f++)
#pragma unroll
        for (int nt = 0; nt < 4; nt++)
#pragma unroll
            for (int j = 0; j < 4; j++) c[f][nt][j] = 0.0f;

    auto loadA = [&](int k0, int buf) {
        int r = tid >> 2;
        int q = tid & 3;
        int bytes = (m0 + r < M) ? 16 : 0;
        cp_async16(&xs[buf][r * AS + q * 4],
                   A + (size_t)(m0 + r) * 128 + k0 + q * 4, bytes);
    };
    auto loadW = [&](int k0, int buf) {
#pragma unroll
        for (int i = 0; i < 2; i++) {
            int idx = tid + i * 256;
            int r = idx >> 5;
            int q = idx & 31;
            cp_async16(&ws[buf][r * WS + q * 4],
                       W + (size_t)(k0 + r) * 128 + q * 4, 16);
        }
    };

    loadA(0, 0);  loadW(0, 0);  asm volatile("cp.async.commit_group;");
    loadA(16, 1); loadW(16, 1); asm volatile("cp.async.commit_group;");

#pragma unroll
    for (int ch = 0; ch < 8; ch++) {
        int buf = ch % 3;
        if (ch < 7) asm volatile("cp.async.wait_group 1;");
        else        asm volatile("cp.async.wait_group 0;");
        __syncthreads();
        if (ch + 2 < 8) {
            int nb = (ch + 2) % 3;
            loadA((ch + 2) * 16, nb);
            loadW((ch + 2) * 16, nb);
            asm volatile("cp.async.commit_group;");
        }

#pragma unroll
        for (int kk = 0; kk < 2; kk++) {
            int kb = kk * 8;
            uint32_t a[2][4];
#pragma unroll
            for (int f = 0; f < 2; f++) {
                int rb = wr + f * 16;
                a[f][0] = rna_tf32(xs[buf][(rb + grp) * AS + kb + sub]);
                a[f][1] = rna_tf32(xs[buf][(rb + grp + 8) * AS + kb + sub]);
                a[f][2] = rna_tf32(xs[buf][(rb + grp) * AS + kb + sub + 4]);
                a[f][3] = rna_tf32(xs[buf][(rb + grp + 8) * AS + kb + sub + 4]);
            }
#pragma unroll
            for (int nt = 0; nt < 4; nt++) {
                uint32_t b0 = rna_tf32(ws[buf][(kb + sub) * WS + wc + nt * 8 + grp]);
                uint32_t b1 = rna_tf32(ws[buf][(kb + sub + 4) * WS + wc + nt * 8 + grp]);
                mma_tf32(c[0][nt][0], c[0][nt][1], c[0][nt][2], c[0][nt][3],
                         a[0][0], a[0][1], a[0][2], a[0][3], b0, b1);
                mma_tf32(c[1][nt][0], c[1][nt][1], c[1][nt][2], c[1][nt][3],
                         a[1][0], a[1][1], a[1][2], a[1][3], b0, b1);
            }
        }
    }

    // epilogue: scale row by dinv[row], emit fp16
#pragma unroll
    for (int f = 0; f < 2; f++) {
        int r0 = m0 + wr + f * 16 + grp;
        int r1 = r0 + 8;
        float d0 = (r0 < M) ? unpack_dinv(g_dc[r0]) : 0.0f;
        float d1 = (r1 < M) ? unpack_dinv(g_dc[r1]) : 0.0f;
#pragma unroll
        for (int nt = 0; nt < 4; nt++) {
            int cb = wc + nt * 8 + 2 * sub;
            if (r0 < M)
                *(half2*)(C + (size_t)r0 * 128 + cb) =
                    __floats2half2_rn(d0 * c[f][nt][0], d0 * c[f][nt][1]);
            if (r1 < M)
                *(half2*)(C + (size_t)r1 * 128 + cb) =
                    __floats2half2_rn(d1 * c[f][nt][2], d1 * c[f][nt][3]);
        }
    }
}

// ------------------- SpMM: out[c,:] = dinv[c]*(sum w*hf[src,:] + hf[c,:]) + b -------
// After destructive scatter: rowptr[c] = END of row c; beg = rowptr[c-1] (0 for c=0).
__global__ void __launch_bounds__(256) k_spmm(const float* __restrict__ bias,
                                              float* outOpt, int N, int doRelu) {
    const uint2* h = (const uint2*)g_hf;
    float* out = outOpt ? outOpt : g_h2;
    int warp = (blockIdx.x * blockDim.x + threadIdx.x) >> 5;
    int lane = threadIdx.x & 31;
    if (warp >= N) return;
    int beg = (warp == 0) ? 0 : g_rowptr[warp - 1];
    int end = g_rowptr[warp];

    float4 acc = make_float4(0.f, 0.f, 0.f, 0.f);
    int e = beg;

#define GATHER_FMA(P, V)                                            \
    do {                                                            \
        float2 f0 = __half22float2(*(const half2*)&(P).x);          \
        float2 f1 = __half22float2(*(const half2*)&(P).y);          \
        acc.x += (V) * f0.x; acc.y += (V) * f0.y;                   \
        acc.z += (V) * f1.x; acc.w += (V) * f1.y;                   \
    } while (0)

    if ((e & 1) && e < end) {
        int2 p = g_edge[e];
        uint2 hv = h[(size_t)p.x * 32 + lane];
        GATHER_FMA(hv, __int_as_float(p.y));
        e++;
    }

    for (; e + 8 <= end; e += 8) {
        int4 q0 = *(const int4*)&g_edge[e + 0];
        int4 q1 = *(const int4*)&g_edge[e + 2];
        int4 q2 = *(const int4*)&g_edge[e + 4];
        int4 q3 = *(const int4*)&g_edge[e + 6];
        uint2 h0 = h[(size_t)q0.x * 32 + lane];
        uint2 h1 = h[(size_t)q0.z * 32 + lane];
        uint2 h2 = h[(size_t)q1.x * 32 + lane];
        uint2 h3 = h[(size_t)q1.z * 32 + lane];
        uint2 h4 = h[(size_t)q2.x * 32 + lane];
        uint2 h5 = h[(size_t)q2.z * 32 + lane];
        uint2 h6 = h[(size_t)q3.x * 32 + lane];
        uint2 h7 = h[(size_t)q3.z * 32 + lane];
        GATHER_FMA(h0, __int_as_float(q0.y));
        GATHER_FMA(h1, __int_as_float(q0.w));
        GATHER_FMA(h2, __int_as_float(q1.y));
        GATHER_FMA(h3, __int_as_float(q1.w));
        GATHER_FMA(h4, __int_as_float(q2.y));
        GATHER_FMA(h5, __int_as_float(q2.w));
        GATHER_FMA(h6, __int_as_float(q3.y));
        GATHER_FMA(h7, __int_as_float(q3.w));
    }

    for (; e + 2 <= end; e += 2) {
        int4 q0 = *(const int4*)&g_edge[e];
        uint2 h0 = h[(size_t)q0.x * 32 + lane];
        uint2 h1 = h[(size_t)q0.z * 32 + lane];
        GATHER_FMA(h0, __int_as_float(q0.y));
        GATHER_FMA(h1, __int_as_float(q0.w));
    }
    if (e < end) {
        int2 p = g_edge[e];
        uint2 hv = h[(size_t)p.x * 32 + lane];
        GATHER_FMA(hv, __int_as_float(p.y));
    }

    // self-loop: own row, weight 1.0 (coalesced read)
    {
        uint2 hv = h[(size_t)warp * 32 + lane];
        GATHER_FMA(hv, 1.0f);
    }
#undef GATHER_FMA

    float dinv_c = unpack_dinv(g_dc[warp]);
    float4 b = ((const float4*)bias)[lane];
    float4 r;
    r.x = dinv_c * acc.x + b.x;
    r.y = dinv_c * acc.y + b.y;
    r.z = dinv_c * acc.z + b.z;
    r.w = dinv_c * acc.w + b.w;
    if (doRelu) {
        r.x = fmaxf(r.x, 0.f);
        r.y = fmaxf(r.y, 0.f);
        r.z = fmaxf(r.z, 0.f);
        r.w = fmaxf(r.w, 0.f);
    }
    *(float4*)(out + (size_t)warp * 128 + lane * 4) = r;
}

// ------------------- launch -------------------
// Fork-join DAG:
//   main: init -> degcount -> [fork] scan1 -> scan2 -> scan3 -> scatter -> [join] spmm1 -> gemm2 -> spmm2
//   side:                       gemm1 (needs only g_dc)
extern "C" void kernel_launch(void* const* d_in, const int* in_sizes, int n_in,
                              void* d_out, int out_size) {
    const float* x  = (const float*)d_in[0];
    const void*  ei = (const void*)d_in[1];
    const float* ew = (const float*)d_in[2];
    const float* W1 = (const float*)d_in[3];
    const float* b1 = (const float*)d_in[4];
    const float* W2 = (const float*)d_in[5];
    const float* b2 = (const float*)d_in[6];
    float* out = (float*)d_out;

    const int E = in_sizes[2];          // 3200000
    const int N = in_sizes[0] / FDIM;   // 100000

    // Created once on the first (uncaptured correctness) call; reused under capture.
    static cudaStream_t s1 = nullptr;
    static cudaEvent_t evFork = nullptr, evJoin = nullptr;
    if (s1 == nullptr) {
        cudaStreamCreateWithFlags(&s1, cudaStreamNonBlocking);
        cudaEventCreateWithFlags(&evFork, cudaEventDisableTiming);
        cudaEventCreateWithFlags(&evJoin, cudaEventDisableTiming);
    }

    int gemmGrid = (N + 63) / 64;
    int spmmGrid = (N * 32 + 255) / 256;
    int nb = (N + SCAN_CHUNK - 1) / SCAN_CHUNK;
    int edgeGrid = ((E + 1) / 2 + 255) / 256;

    k_init<<<(N + 255) / 256, 256>>>(N);
    k_degcount<<<edgeGrid, 256>>>(ei, ew, E, N);

    // fork: gemm1 only needs g_dc (degcount) — overlap with CSR build
    cudaEventRecord(evFork, 0);
    cudaStreamWaitEvent(s1, evFork, 0);
    k_gemm<<<gemmGrid, 256, 0, s1>>>(x, W1, N);
    cudaEventRecord(evJoin, s1);

    k_scan1<<<nb, 256>>>(N);
    k_scan2<<<1, MAX_SCAN_BLOCKS>>>(nb);
    k_scan3<<<(N + 255) / 256, 256>>>(N);
    k_scatter<<<edgeGrid, 256>>>(ei, ew, E, N);

    // join: spmm1 needs both scatter (CSR) and gemm1 (g_hf)
    cudaStreamWaitEvent(0, evJoin, 0);
    k_spmm<<<spmmGrid, 256>>>(b1, nullptr, N, 1);   // g_hf -> g_h2
    k_gemm<<<gemmGrid, 256>>>(nullptr, W2, N);      // g_h2 -> g_hf
    k_spmm<<<spmmGrid, 256>>>(b2, out, N, 0);       // g_hf -> out
}